// round 1
// baseline (speedup 1.0000x reference)
#include <cuda_runtime.h>
#include <math.h>

#define NRAYS 8192
#define SMAX  64
#define EMB   32
#define HID   128
#define VDIM  27        // 3 + 6*4 view PE
#define C1DIM 64
#define RPB   8         // rays per block
#define NBLK  (NRAYS / RPB)
#define NTHR  256

// ---- shared memory layout (float offsets) ----
// weights
#define OFF_W1    0                    // 32*128   = 4096
#define OFF_W2    4096                 // 128*128  = 16384
#define OFF_WF    20480                // 128*128  = 16384
#define OFF_WC1   36864                // 155*64   = 9920
#define OFF_WSIG  46784                // 128
#define OFF_WC2   46912                // 64*3 = 192
#define OFF_WPTS  47104                // 3*32 = 96
#define OFF_B1    47200                // 128
#define OFF_B2    47328                // 128
#define OFF_BF    47456                // 128
#define OFF_BC1   47584                // 64
#define OFF_BC2   47648                // 3
#define OFF_BSIG  47651                // 1
#define OFF_VEMB  47652                // 28 (27 used)
// per-ray scratch
#define OFF_TV    47680                // 64
#define OFF_DI    47744                // 64
#define OFF_SIG   47808                // 64
#define OFF_RGB   47872                // 64*3 = 192
// per-group activation buffers, row stride 12 floats (48B, conflict-free, f4-aligned)
#define OFF_BUFA  48064                // 2 * 128*12 = 3072
#define OFF_BUFB  51136                // 2 * 128*12 = 3072
#define OFF_BUFC  54208                // 2 * 64*12  = 1536
#define OFF_INT   55744                // ints: svec(64), sidx(64), c01(2), mcount(1)
#define SMEM_FLOATS (OFF_INT + 132)
#define SMEM_BYTES  (SMEM_FLOATS * 4)

__device__ __forceinline__ void smem_copy(float* dst, const float* __restrict__ src, int n, int tid) {
    for (int i = tid; i < n; i += NTHR) dst[i] = src[i];
}

// One MLP layer for an 8-point batch. X: [K][12] activations (broadcast reads),
// W: [K][HID] k-major in smem, thread gt owns hidden unit gt, 8 accumulators.
__device__ __forceinline__ void mlp_layer(const float* __restrict__ X, const float* __restrict__ W,
                                          const float* __restrict__ bias, float* __restrict__ Y,
                                          int K, int gt, bool doRelu) {
    float b = bias[gt];
    float a0 = b, a1 = b, a2 = b, a3 = b, a4 = b, a5 = b, a6 = b, a7 = b;
#pragma unroll 4
    for (int k = 0; k < K; k++) {
        float w = W[k * HID + gt];
        float4 x0 = *reinterpret_cast<const float4*>(X + k * 12);
        float4 x1 = *reinterpret_cast<const float4*>(X + k * 12 + 4);
        a0 += w * x0.x; a1 += w * x0.y; a2 += w * x0.z; a3 += w * x0.w;
        a4 += w * x1.x; a5 += w * x1.y; a6 += w * x1.z; a7 += w * x1.w;
    }
    if (doRelu) {
        a0 = fmaxf(a0, 0.f); a1 = fmaxf(a1, 0.f); a2 = fmaxf(a2, 0.f); a3 = fmaxf(a3, 0.f);
        a4 = fmaxf(a4, 0.f); a5 = fmaxf(a5, 0.f); a6 = fmaxf(a6, 0.f); a7 = fmaxf(a7, 0.f);
    }
    float4* yr = reinterpret_cast<float4*>(Y + gt * 12);
    yr[0] = make_float4(a0, a1, a2, a3);
    yr[1] = make_float4(a4, a5, a6, a7);
}

__global__ void __launch_bounds__(NTHR, 1)
nsvf_kernel(const float* __restrict__ rays_d, const float* __restrict__ pts,
            const float* __restrict__ t_vals, const float* __restrict__ dists,
            const int* __restrict__ p2v, const float* __restrict__ vox_emb,
            const float* __restrict__ Wpts, const float* __restrict__ W1, const float* __restrict__ b1,
            const float* __restrict__ W2, const float* __restrict__ b2,
            const float* __restrict__ Wsig, const float* __restrict__ bsig,
            const float* __restrict__ Wfeat, const float* __restrict__ bfeat,
            const float* __restrict__ Wc1, const float* __restrict__ bc1,
            const float* __restrict__ Wc2, const float* __restrict__ bc2,
            float* __restrict__ out) {
    extern __shared__ float sm[];
    const int tid = threadIdx.x;
    const int g   = tid >> 7;        // group 0/1
    const int gt  = tid & 127;       // thread within group

    // stage all weights once per block
    smem_copy(sm + OFF_W1,   W1,   EMB * HID, tid);
    smem_copy(sm + OFF_W2,   W2,   HID * HID, tid);
    smem_copy(sm + OFF_WF,   Wfeat, HID * HID, tid);
    smem_copy(sm + OFF_WC1,  Wc1,  (HID + VDIM) * C1DIM, tid);
    smem_copy(sm + OFF_WSIG, Wsig, HID, tid);
    smem_copy(sm + OFF_WC2,  Wc2,  C1DIM * 3, tid);
    smem_copy(sm + OFF_WPTS, Wpts, 3 * EMB, tid);
    smem_copy(sm + OFF_B1,   b1,   HID, tid);
    smem_copy(sm + OFF_B2,   b2,   HID, tid);
    smem_copy(sm + OFF_BF,   bfeat, HID, tid);
    smem_copy(sm + OFF_BC1,  bc1,  C1DIM, tid);
    smem_copy(sm + OFF_BC2,  bc2,  3, tid);
    smem_copy(sm + OFF_BSIG, bsig, 1, tid);

    int*   ip    = (int*)(sm + OFF_INT);
    int*   svec  = ip;
    int*   sidx  = ip + 64;
    int*   c01   = ip + 128;
    int*   mcnt  = ip + 130;
    float* A     = sm + OFF_BUFA + g * 1536;
    float* B     = sm + OFF_BUFB + g * 1536;
    float* C     = sm + OFF_BUFC + g * 768;
    float* vembs = sm + OFF_VEMB;

    for (int r = 0; r < RPB; r++) {
        const int ray = blockIdx.x * RPB + r;
        __syncthreads();   // previous ray fully done before overwriting scratch

        // ---- per-ray staging: t/dists, view PE, valid-sample compaction ----
        int  myv = 0; bool myvalid = false; unsigned bmask = 0;
        if (tid < 64) {
            sm[OFF_TV + tid] = t_vals[ray * SMAX + tid];
            sm[OFF_DI + tid] = dists[ray * SMAX + tid];
            myv = p2v[ray * SMAX + tid];
            myvalid = (myv >= 0);
            bmask = __ballot_sync(0xffffffffu, myvalid);
            if ((tid & 31) == 0) c01[tid >> 5] = __popc(bmask);
        } else if (tid < 64 + VDIM) {
            int j = tid - 64;
            if (j < 3) vembs[j] = rays_d[ray * 3 + j];
            else {
                int a = j - 3; int aa = a % 12; int dj = aa >> 2; int l = aa & 3;
                float d = rays_d[ray * 3 + dj];
                float ang = d * (float)(1 << l);
                vembs[j] = (a >= 12) ? cosf(ang) : sinf(ang);
            }
        }
        __syncthreads();
        if (tid < 64 && myvalid) {
            int pos = __popc(bmask & ((1u << (tid & 31)) - 1)) + ((tid >= 32) ? c01[0] : 0);
            svec[pos] = tid;
            sidx[pos] = myv;
        }
        if (tid == 0) *mcnt = c01[0] + c01[1];
        __syncthreads();
        const int m = *mcnt;
        const int maxb = (m + 7) >> 3;
        const int iters = (maxb + 1) >> 1;

        for (int it = 0; it < iters; it++) {
            const int bb = it * 2 + g;
            const int np = (bb < maxb) ? min(8, m - bb * 8) : 0;

            // ---- voxel embed + positional lift -> A[k][p], k<32 ----
            if (np > 0) {
#pragma unroll
                for (int e2 = 0; e2 < 2; e2++) {
                    int e = gt + e2 * 128;
                    int k = e >> 3, p = e & 7;
                    float val = 0.f;
                    if (p < np) {
                        int s = svec[bb * 8 + p];
                        int v = sidx[bb * 8 + p];
                        const float* pp = pts + (size_t)(ray * SMAX + s) * 3;
                        float p0 = pp[0], p1 = pp[1], p2 = pp[2];
                        val = vox_emb[(size_t)v * EMB + k]
                            + p0 * sm[OFF_WPTS + k]
                            + p1 * sm[OFF_WPTS + 32 + k]
                            + p2 * sm[OFF_WPTS + 64 + k];
                    }
                    A[k * 12 + p] = val;
                }
            }
            __syncthreads();
            if (np > 0) mlp_layer(A, sm + OFF_W1, sm + OFF_B1, B, EMB, gt, true);   // h1
            __syncthreads();
            if (np > 0) mlp_layer(B, sm + OFF_W2, sm + OFF_B2, A, HID, gt, true);   // h2 (in A)
            __syncthreads();
            if (np > 0) mlp_layer(A, sm + OFF_WF, sm + OFF_BF, B, HID, gt, false);  // feat (in B)
            __syncthreads();
            // ---- color layer 1: [feat(128) | vemb(27)] @ Wc1 -> C[u][p] ----
            if (np > 0) {
                int u = gt & 63, pg = gt >> 6;
                float bcv = sm[OFF_BC1 + u];
                float a0 = bcv, a1 = bcv, a2 = bcv, a3 = bcv;
#pragma unroll 4
                for (int k = 0; k < HID; k++) {
                    float w = sm[OFF_WC1 + k * C1DIM + u];
                    float4 x = *reinterpret_cast<const float4*>(B + k * 12 + pg * 4);
                    a0 += w * x.x; a1 += w * x.y; a2 += w * x.z; a3 += w * x.w;
                }
#pragma unroll
                for (int k = 0; k < VDIM; k++) {
                    float t = sm[OFF_WC1 + (HID + k) * C1DIM + u] * vembs[k];
                    a0 += t; a1 += t; a2 += t; a3 += t;
                }
                a0 = fmaxf(a0, 0.f); a1 = fmaxf(a1, 0.f); a2 = fmaxf(a2, 0.f); a3 = fmaxf(a3, 0.f);
                *reinterpret_cast<float4*>(C + u * 12 + pg * 4) = make_float4(a0, a1, a2, a3);
            }
            __syncthreads();
            // ---- color layer 2 (threads 0..23) and sigma (threads 64..71) ----
            if (np > 0) {
                if (gt < 24) {
                    int p = gt / 3, ch = gt % 3;
                    if (p < np) {
                        float a = sm[OFF_BC2 + ch];
#pragma unroll 4
                        for (int u = 0; u < C1DIM; u++) a += C[u * 12 + p] * sm[OFF_WC2 + u * 3 + ch];
                        sm[OFF_RGB + svec[bb * 8 + p] * 3 + ch] = a;
                    }
                } else if (gt >= 64 && gt < 72) {
                    int p = gt - 64;
                    if (p < np) {
                        float a = sm[OFF_BSIG];
#pragma unroll 4
                        for (int k = 0; k < HID; k++) a += A[k * 12 + p] * sm[OFF_WSIG + k];
                        sm[OFF_SIG + svec[bb * 8 + p]] = a;
                    }
                }
            }
            __syncthreads();
        }

        // ---- volumetric render (sequential transmittance), thread 0 ----
        if (tid == 0) {
            float fsum = 0.f, c0 = 0.f, c1v = 0.f, c2v = 0.f, acc = 0.f, depth = 0.f;
            for (int i = 0; i < m; i++) {
                int s = svec[i];
                float fe = fmaxf(sm[OFF_SIG + s], 0.f) * sm[OFF_DI + s];
                float T  = expf(-fsum);
                float w  = (1.f - expf(-fe)) * T;
                c0 += w * (sm[OFF_RGB + s * 3 + 0] + 1.f) * 0.5f;
                c1v += w * (sm[OFF_RGB + s * 3 + 1] + 1.f) * 0.5f;
                c2v += w * (sm[OFF_RGB + s * 3 + 2] + 1.f) * 0.5f;
                acc += w;
                depth += w * sm[OFF_TV + s];
                fsum += fe;
            }
            float disp;
            if (m > 0) disp = 1.f / fmaxf(1e-10f, depth / fmaxf(acc, 1e-10f));
            else { disp = 0.f; acc = 0.f; c0 = c1v = c2v = 0.f; }
            out[ray * 3 + 0] = c0;
            out[ray * 3 + 1] = c1v;
            out[ray * 3 + 2] = c2v;
            out[NRAYS * 3 + ray] = disp;
            out[NRAYS * 4 + ray] = acc;
        }
    }
}

extern "C" void kernel_launch(void* const* d_in, const int* in_sizes, int n_in,
                              void* d_out, int out_size) {
    const float *rays_d = 0, *pts = 0, *t_vals = 0, *dists = 0, *vox = 0, *Wpts = 0;
    const float *W1 = 0, *b1 = 0, *W2 = 0, *b2 = 0, *Wsig = 0, *bsig = 0;
    const float *Wfeat = 0, *bfeat = 0, *Wc1 = 0, *bc1 = 0, *Wc2 = 0, *bc2 = 0;
    const int* p2v = 0;
    int n524 = 0, n16384 = 0, n128 = 0;
    for (int i = 0; i < n_in; i++) {
        const void* p = d_in[i];
        switch (in_sizes[i]) {
            case 24576:   rays_d = (const float*)p; break;
            case 1572864: pts    = (const float*)p; break;
            case 524288:
                if (n524 == 0) t_vals = (const float*)p;
                else if (n524 == 1) dists = (const float*)p;
                else p2v = (const int*)p;
                n524++; break;
            case 3200000: vox = (const float*)p; break;
            case 96:    Wpts = (const float*)p; break;
            case 4096:  W1 = (const float*)p; break;
            case 128:
                if (n128 == 0) b1 = (const float*)p;
                else if (n128 == 1) b2 = (const float*)p;
                else if (n128 == 2) Wsig = (const float*)p;
                else bfeat = (const float*)p;
                n128++; break;
            case 16384:
                if (n16384 == 0) W2 = (const float*)p; else Wfeat = (const float*)p;
                n16384++; break;
            case 1:    bsig = (const float*)p; break;
            case 9920: Wc1 = (const float*)p; break;
            case 64:   bc1 = (const float*)p; break;
            case 192:  Wc2 = (const float*)p; break;
            case 3:    bc2 = (const float*)p; break;
            default: break; // 8192 = ray_hits (derived from p2v instead)
        }
    }
    cudaFuncSetAttribute(nsvf_kernel, cudaFuncAttributeMaxDynamicSharedMemorySize, SMEM_BYTES);
    nsvf_kernel<<<NBLK, NTHR, SMEM_BYTES>>>(rays_d, pts, t_vals, dists, p2v, vox,
                                            Wpts, W1, b1, W2, b2, Wsig, bsig,
                                            Wfeat, bfeat, Wc1, bc1, Wc2, bc2,
                                            (float*)d_out);
}

// round 2
// speedup vs baseline: 1.0004x; 1.0004x over previous
#include <cuda_runtime.h>
#include <math.h>

#define NRAYS 8192
#define SMAX  64
#define EMB   32
#define HID   128
#define VDIM  27        // 3 + 6*4 view PE
#define C1DIM 64
#define RPB   8         // rays per block
#define NBLK  (NRAYS / RPB)
#define NTHR  256

// ---- shared memory layout (float offsets) ----
// weights
#define OFF_W1    0                    // 32*128   = 4096
#define OFF_W2    4096                 // 128*128  = 16384
#define OFF_WF    20480                // 128*128  = 16384
#define OFF_WC1   36864                // 155*64   = 9920
#define OFF_WSIG  46784                // 128
#define OFF_WC2   46912                // 64*3 = 192
#define OFF_WPTS  47104                // 3*32 = 96
#define OFF_B1    47200                // 128
#define OFF_B2    47328                // 128
#define OFF_BF    47456                // 128
#define OFF_BC1   47584                // 64
#define OFF_BC2   47648                // 3
#define OFF_BSIG  47651                // 1
#define OFF_VEMB  47652                // 28 (27 used)
// per-ray scratch
#define OFF_TV    47680                // 64
#define OFF_DI    47744                // 64
#define OFF_SIG   47808                // 64
#define OFF_RGB   47872                // 64*3 = 192
// per-group activation buffers, row stride 12 floats (48B, conflict-free, f4-aligned)
#define OFF_BUFA  48064                // 2 * 128*12 = 3072
#define OFF_BUFB  51136                // 2 * 128*12 = 3072
#define OFF_BUFC  54208                // 2 * 64*12  = 1536
#define OFF_INT   55744                // ints: svec(64), sidx(64), c01(2), mcount(1)
#define SMEM_FLOATS (OFF_INT + 132)
#define SMEM_BYTES  (SMEM_FLOATS * 4)

__device__ __forceinline__ void smem_copy(float* dst, const float* __restrict__ src, int n, int tid) {
    for (int i = tid; i < n; i += NTHR) dst[i] = src[i];
}

// One MLP layer for an 8-point batch. X: [K][12] activations (broadcast reads),
// W: [K][HID] k-major in smem, thread gt owns hidden unit gt, 8 accumulators.
__device__ __forceinline__ void mlp_layer(const float* __restrict__ X, const float* __restrict__ W,
                                          const float* __restrict__ bias, float* __restrict__ Y,
                                          int K, int gt, bool doRelu) {
    float b = bias[gt];
    float a0 = b, a1 = b, a2 = b, a3 = b, a4 = b, a5 = b, a6 = b, a7 = b;
#pragma unroll 4
    for (int k = 0; k < K; k++) {
        float w = W[k * HID + gt];
        float4 x0 = *reinterpret_cast<const float4*>(X + k * 12);
        float4 x1 = *reinterpret_cast<const float4*>(X + k * 12 + 4);
        a0 += w * x0.x; a1 += w * x0.y; a2 += w * x0.z; a3 += w * x0.w;
        a4 += w * x1.x; a5 += w * x1.y; a6 += w * x1.z; a7 += w * x1.w;
    }
    if (doRelu) {
        a0 = fmaxf(a0, 0.f); a1 = fmaxf(a1, 0.f); a2 = fmaxf(a2, 0.f); a3 = fmaxf(a3, 0.f);
        a4 = fmaxf(a4, 0.f); a5 = fmaxf(a5, 0.f); a6 = fmaxf(a6, 0.f); a7 = fmaxf(a7, 0.f);
    }
    float4* yr = reinterpret_cast<float4*>(Y + gt * 12);
    yr[0] = make_float4(a0, a1, a2, a3);
    yr[1] = make_float4(a4, a5, a6, a7);
}

__global__ void __launch_bounds__(NTHR, 1)
nsvf_kernel(const float* __restrict__ rays_d, const float* __restrict__ pts,
            const float* __restrict__ t_vals, const float* __restrict__ dists,
            const int* __restrict__ p2v, const float* __restrict__ vox_emb,
            const float* __restrict__ Wpts, const float* __restrict__ W1, const float* __restrict__ b1,
            const float* __restrict__ W2, const float* __restrict__ b2,
            const float* __restrict__ Wsig, const float* __restrict__ bsig,
            const float* __restrict__ Wfeat, const float* __restrict__ bfeat,
            const float* __restrict__ Wc1, const float* __restrict__ bc1,
            const float* __restrict__ Wc2, const float* __restrict__ bc2,
            float* __restrict__ out) {
    extern __shared__ float sm[];
    const int tid = threadIdx.x;
    const int g   = tid >> 7;        // group 0/1
    const int gt  = tid & 127;       // thread within group

    // stage all weights once per block
    smem_copy(sm + OFF_W1,   W1,   EMB * HID, tid);
    smem_copy(sm + OFF_W2,   W2,   HID * HID, tid);
    smem_copy(sm + OFF_WF,   Wfeat, HID * HID, tid);
    smem_copy(sm + OFF_WC1,  Wc1,  (HID + VDIM) * C1DIM, tid);
    smem_copy(sm + OFF_WSIG, Wsig, HID, tid);
    smem_copy(sm + OFF_WC2,  Wc2,  C1DIM * 3, tid);
    smem_copy(sm + OFF_WPTS, Wpts, 3 * EMB, tid);
    smem_copy(sm + OFF_B1,   b1,   HID, tid);
    smem_copy(sm + OFF_B2,   b2,   HID, tid);
    smem_copy(sm + OFF_BF,   bfeat, HID, tid);
    smem_copy(sm + OFF_BC1,  bc1,  C1DIM, tid);
    smem_copy(sm + OFF_BC2,  bc2,  3, tid);
    smem_copy(sm + OFF_BSIG, bsig, 1, tid);

    int*   ip    = (int*)(sm + OFF_INT);
    int*   svec  = ip;
    int*   sidx  = ip + 64;
    int*   c01   = ip + 128;
    int*   mcnt  = ip + 130;
    float* A     = sm + OFF_BUFA + g * 1536;
    float* B     = sm + OFF_BUFB + g * 1536;
    float* C     = sm + OFF_BUFC + g * 768;
    float* vembs = sm + OFF_VEMB;

    for (int r = 0; r < RPB; r++) {
        const int ray = blockIdx.x * RPB + r;
        __syncthreads();   // previous ray fully done before overwriting scratch

        // ---- per-ray staging: t/dists, view PE, valid-sample compaction ----
        int  myv = 0; bool myvalid = false; unsigned bmask = 0;
        if (tid < 64) {
            sm[OFF_TV + tid] = t_vals[ray * SMAX + tid];
            sm[OFF_DI + tid] = dists[ray * SMAX + tid];
            myv = p2v[ray * SMAX + tid];
            myvalid = (myv >= 0);
            bmask = __ballot_sync(0xffffffffu, myvalid);
            if ((tid & 31) == 0) c01[tid >> 5] = __popc(bmask);
        } else if (tid < 64 + VDIM) {
            int j = tid - 64;
            if (j < 3) vembs[j] = rays_d[ray * 3 + j];
            else {
                int a = j - 3; int aa = a % 12; int dj = aa >> 2; int l = aa & 3;
                float d = rays_d[ray * 3 + dj];
                float ang = d * (float)(1 << l);
                vembs[j] = (a >= 12) ? cosf(ang) : sinf(ang);
            }
        }
        __syncthreads();
        if (tid < 64 && myvalid) {
            int pos = __popc(bmask & ((1u << (tid & 31)) - 1)) + ((tid >= 32) ? c01[0] : 0);
            svec[pos] = tid;
            sidx[pos] = myv;
        }
        if (tid == 0) *mcnt = c01[0] + c01[1];
        __syncthreads();
        const int m = *mcnt;
        const int maxb = (m + 7) >> 3;
        const int iters = (maxb + 1) >> 1;

        for (int it = 0; it < iters; it++) {
            const int bb = it * 2 + g;
            const int np = (bb < maxb) ? min(8, m - bb * 8) : 0;

            // ---- voxel embed + positional lift -> A[k][p], k<32 ----
            if (np > 0) {
#pragma unroll
                for (int e2 = 0; e2 < 2; e2++) {
                    int e = gt + e2 * 128;
                    int k = e >> 3, p = e & 7;
                    float val = 0.f;
                    if (p < np) {
                        int s = svec[bb * 8 + p];
                        int v = sidx[bb * 8 + p];
                        const float* pp = pts + (size_t)(ray * SMAX + s) * 3;
                        float p0 = pp[0], p1 = pp[1], p2 = pp[2];
                        val = vox_emb[(size_t)v * EMB + k]
                            + p0 * sm[OFF_WPTS + k]
                            + p1 * sm[OFF_WPTS + 32 + k]
                            + p2 * sm[OFF_WPTS + 64 + k];
                    }
                    A[k * 12 + p] = val;
                }
            }
            __syncthreads();
            if (np > 0) mlp_layer(A, sm + OFF_W1, sm + OFF_B1, B, EMB, gt, true);   // h1
            __syncthreads();
            if (np > 0) mlp_layer(B, sm + OFF_W2, sm + OFF_B2, A, HID, gt, true);   // h2 (in A)
            __syncthreads();
            if (np > 0) mlp_layer(A, sm + OFF_WF, sm + OFF_BF, B, HID, gt, false);  // feat (in B)
            __syncthreads();
            // ---- color layer 1: [feat(128) | vemb(27)] @ Wc1 -> C[u][p] ----
            if (np > 0) {
                int u = gt & 63, pg = gt >> 6;
                float bcv = sm[OFF_BC1 + u];
                float a0 = bcv, a1 = bcv, a2 = bcv, a3 = bcv;
#pragma unroll 4
                for (int k = 0; k < HID; k++) {
                    float w = sm[OFF_WC1 + k * C1DIM + u];
                    float4 x = *reinterpret_cast<const float4*>(B + k * 12 + pg * 4);
                    a0 += w * x.x; a1 += w * x.y; a2 += w * x.z; a3 += w * x.w;
                }
#pragma unroll
                for (int k = 0; k < VDIM; k++) {
                    float t = sm[OFF_WC1 + (HID + k) * C1DIM + u] * vembs[k];
                    a0 += t; a1 += t; a2 += t; a3 += t;
                }
                a0 = fmaxf(a0, 0.f); a1 = fmaxf(a1, 0.f); a2 = fmaxf(a2, 0.f); a3 = fmaxf(a3, 0.f);
                *reinterpret_cast<float4*>(C + u * 12 + pg * 4) = make_float4(a0, a1, a2, a3);
            }
            __syncthreads();
            // ---- color layer 2 (threads 0..23) and sigma (threads 64..71) ----
            if (np > 0) {
                if (gt < 24) {
                    int p = gt / 3, ch = gt % 3;
                    if (p < np) {
                        float a = sm[OFF_BC2 + ch];
#pragma unroll 4
                        for (int u = 0; u < C1DIM; u++) a += C[u * 12 + p] * sm[OFF_WC2 + u * 3 + ch];
                        sm[OFF_RGB + svec[bb * 8 + p] * 3 + ch] = a;
                    }
                } else if (gt >= 64 && gt < 72) {
                    int p = gt - 64;
                    if (p < np) {
                        float a = sm[OFF_BSIG];
#pragma unroll 4
                        for (int k = 0; k < HID; k++) a += A[k * 12 + p] * sm[OFF_WSIG + k];
                        sm[OFF_SIG + svec[bb * 8 + p]] = a;
                    }
                }
            }
            __syncthreads();
        }

        // ---- volumetric render (sequential transmittance), thread 0 ----
        if (tid == 0) {
            float fsum = 0.f, c0 = 0.f, c1v = 0.f, c2v = 0.f, acc = 0.f, depth = 0.f;
            for (int i = 0; i < m; i++) {
                int s = svec[i];
                float fe = fmaxf(sm[OFF_SIG + s], 0.f) * sm[OFF_DI + s];
                float T  = expf(-fsum);
                float w  = (1.f - expf(-fe)) * T;
                c0 += w * (sm[OFF_RGB + s * 3 + 0] + 1.f) * 0.5f;
                c1v += w * (sm[OFF_RGB + s * 3 + 1] + 1.f) * 0.5f;
                c2v += w * (sm[OFF_RGB + s * 3 + 2] + 1.f) * 0.5f;
                acc += w;
                depth += w * sm[OFF_TV + s];
                fsum += fe;
            }
            float disp;
            if (m > 0) disp = 1.f / fmaxf(1e-10f, depth / fmaxf(acc, 1e-10f));
            else { disp = 0.f; acc = 0.f; c0 = c1v = c2v = 0.f; }
            out[ray * 3 + 0] = c0;
            out[ray * 3 + 1] = c1v;
            out[ray * 3 + 2] = c2v;
            out[NRAYS * 3 + ray] = disp;
            out[NRAYS * 4 + ray] = acc;
        }
    }
}

extern "C" void kernel_launch(void* const* d_in, const int* in_sizes, int n_in,
                              void* d_out, int out_size) {
    const float *rays_d = 0, *pts = 0, *t_vals = 0, *dists = 0, *vox = 0, *Wpts = 0;
    const float *W1 = 0, *b1 = 0, *W2 = 0, *b2 = 0, *Wsig = 0, *bsig = 0;
    const float *Wfeat = 0, *bfeat = 0, *Wc1 = 0, *bc1 = 0, *Wc2 = 0, *bc2 = 0;
    const int* p2v = 0;
    int n524 = 0, n16384 = 0, n128 = 0;
    for (int i = 0; i < n_in; i++) {
        const void* p = d_in[i];
        switch (in_sizes[i]) {
            case 24576:   rays_d = (const float*)p; break;
            case 1572864: pts    = (const float*)p; break;
            case 524288:
                if (n524 == 0) t_vals = (const float*)p;
                else if (n524 == 1) dists = (const float*)p;
                else p2v = (const int*)p;
                n524++; break;
            case 3200000: vox = (const float*)p; break;
            case 96:    Wpts = (const float*)p; break;
            case 4096:  W1 = (const float*)p; break;
            case 128:
                if (n128 == 0) b1 = (const float*)p;
                else if (n128 == 1) b2 = (const float*)p;
                else if (n128 == 2) Wsig = (const float*)p;
                else bfeat = (const float*)p;
                n128++; break;
            case 16384:
                if (n16384 == 0) W2 = (const float*)p; else Wfeat = (const float*)p;
                n16384++; break;
            case 1:    bsig = (const float*)p; break;
            case 9920: Wc1 = (const float*)p; break;
            case 64:   bc1 = (const float*)p; break;
            case 192:  Wc2 = (const float*)p; break;
            case 3:    bc2 = (const float*)p; break;
            default: break; // 8192 = ray_hits (derived from p2v instead)
        }
    }
    cudaFuncSetAttribute(nsvf_kernel, cudaFuncAttributeMaxDynamicSharedMemorySize, SMEM_BYTES);
    nsvf_kernel<<<NBLK, NTHR, SMEM_BYTES>>>(rays_d, pts, t_vals, dists, p2v, vox,
                                            Wpts, W1, b1, W2, b2, Wsig, bsig,
                                            Wfeat, bfeat, Wc1, bc1, Wc2, bc2,
                                            (float*)d_out);
}

// round 3
// speedup vs baseline: 1.7894x; 1.7887x over previous
#include <cuda_runtime.h>
#include <math.h>
#include <stdint.h>

#define NRAYS 8192
#define SMAX  64
#define EMB   32
#define HID   128
#define PSTR  68
#define NTHR  256

typedef unsigned long long u64;

__device__ int   g_cnt[NRAYS];
__device__ int   g_off[NRAYS + 1];
__device__ int   g_pray[NRAYS * SMAX];
__device__ float g_vemb[NRAYS * 27];
__device__ float g_vb[NRAYS * 64];
__device__ float g_sig[NRAYS * SMAX];
__device__ float g_rgbp[NRAYS * SMAX * 3];
__device__ int   g_tile_ctr;

__device__ __forceinline__ uint32_t sptr(const void* p) {
    return (uint32_t)__cvta_generic_to_shared(p);
}
__device__ __forceinline__ u64 pack2(float lo, float hi) {
    u64 r;
    asm("mov.b64 %0, {%1,%2};" : "=l"(r) : "r"(__float_as_uint(lo)), "r"(__float_as_uint(hi)));
    return r;
}
__device__ __forceinline__ void unpack2(float& lo, float& hi, u64 v) {
    unsigned a, b;
    asm("mov.b64 {%0,%1}, %2;" : "=r"(a), "=r"(b) : "l"(v));
    lo = __uint_as_float(a); hi = __uint_as_float(b);
}
__device__ __forceinline__ void ffma2(u64& d, u64 a, u64 b) {
    asm("fma.rn.f32x2 %0, %1, %2, %0;" : "+l"(d) : "l"(a), "l"(b));
}
__device__ __forceinline__ void lds_v2u64(u64& a, u64& b, uint32_t addr) {
    asm volatile("ld.shared.v2.u64 {%0,%1}, [%2];" : "=l"(a), "=l"(b) : "r"(addr));
}
__device__ __forceinline__ void lds_f4(float4& v, uint32_t a) {
    asm volatile("ld.shared.v4.f32 {%0,%1,%2,%3}, [%4];"
                 : "=f"(v.x), "=f"(v.y), "=f"(v.z), "=f"(v.w) : "r"(a));
}
__device__ __forceinline__ void lds_f2(float2& v, uint32_t a) {
    asm volatile("ld.shared.v2.f32 {%0,%1}, [%2];" : "=f"(v.x), "=f"(v.y) : "r"(a));
}

// ---------------- setup kernels ----------------
__global__ void prep_ray_kernel(const int* __restrict__ p2v, const float* __restrict__ rays_d) {
    int r = blockIdx.x * blockDim.x + threadIdx.x;
    if (r >= NRAYS) return;
    int lo = 0, hi = SMAX;
    while (lo < hi) {                       // valid samples form a prefix
        int mid = (lo + hi) >> 1;
        if (p2v[r * SMAX + mid] >= 0) lo = mid + 1; else hi = mid;
    }
    g_cnt[r] = lo;
    float dv[3] = {rays_d[r * 3], rays_d[r * 3 + 1], rays_d[r * 3 + 2]};
    g_vemb[r * 27 + 0] = dv[0]; g_vemb[r * 27 + 1] = dv[1]; g_vemb[r * 27 + 2] = dv[2];
#pragma unroll
    for (int i = 0; i < 3; i++)
#pragma unroll
        for (int l = 0; l < 4; l++) {
            float ang = dv[i] * (float)(1 << l);
            g_vemb[r * 27 + 3 + i * 4 + l]  = sinf(ang);
            g_vemb[r * 27 + 15 + i * 4 + l] = cosf(ang);
        }
}

__global__ void scan_kernel() {              // 1 block, 1024 threads, 8 rays each
    __shared__ int wsum[32];
    int t = threadIdx.x;
    int v[8]; int s = 0;
#pragma unroll
    for (int i = 0; i < 8; i++) { v[i] = g_cnt[t * 8 + i]; s += v[i]; }
    int lane = t & 31, wid = t >> 5;
    int x = s;
#pragma unroll
    for (int d = 1; d < 32; d <<= 1) { int y = __shfl_up_sync(0xffffffffu, x, d); if (lane >= d) x += y; }
    if (lane == 31) wsum[wid] = x;
    __syncthreads();
    if (wid == 0) {
        int y = wsum[lane];
#pragma unroll
        for (int d = 1; d < 32; d <<= 1) { int z = __shfl_up_sync(0xffffffffu, y, d); if (lane >= d) y += z; }
        wsum[lane] = y;
    }
    __syncthreads();
    int run = (wid > 0 ? wsum[wid - 1] : 0) + x - s;
#pragma unroll
    for (int i = 0; i < 8; i++) { g_off[t * 8 + i] = run; run += v[i]; }
    if (t == 1023) { g_off[NRAYS] = run; g_tile_ctr = 0; }
}

__global__ void vb_kernel(const float* __restrict__ Wc1, const float* __restrict__ bc1) {
    int gid = blockIdx.x * blockDim.x + threadIdx.x;
    if (gid >= NRAYS * 64) return;
    int r = gid >> 6, u = gid & 63;
    float a = bc1[u];
#pragma unroll
    for (int k = 0; k < 27; k++)
        a += Wc1[(HID + k) * 64 + u] * g_vemb[r * 27 + k];
    g_vb[gid] = a;
}

__global__ void pray_kernel() {              // grid NRAYS/4, 256 thr
    int r = blockIdx.x * 4 + (threadIdx.x >> 6);
    int t = threadIdx.x & 63;
    int o = g_off[r], c = g_off[r + 1] - o;
    if (t < c) g_pray[o + t] = r;
}

// ---------------- fused MLP ----------------
template <int M>
__device__ __forceinline__ void stage_chunk(float* dst, const float4* pf, int tid) {
    constexpr int LPT = M / 16;
#pragma unroll
    for (int f = 0; f < LPT / 4; f++)
        *reinterpret_cast<float4*>(dst + tid * LPT + 4 * f) = pf[f];
}

template <int M, int K, bool RELU, bool C1>
__device__ __forceinline__ void gemm_layer(
    const float* __restrict__ Wg, const float* __restrict__ Xs, float* __restrict__ Ys,
    const float* __restrict__ bias_s, const int* __restrict__ rays_s,
    float* __restrict__ Wbuf, int tid) {
    constexpr int NC = K / 16;
    constexpr int RT = M / 32;
    constexpr int LPT = M / 16;
    const int mg = tid & 31, pg = tid >> 5;
    const int m0 = mg * RT, p0 = pg * 8;

    u64 acc[RT][4];
    if (C1) {
#pragma unroll
        for (int r = 0; r < RT; r++)
#pragma unroll
            for (int q = 0; q < 4; q++)
                acc[r][q] = pack2(g_vb[rays_s[p0 + 2 * q] * 64 + m0 + r],
                                  g_vb[rays_s[p0 + 2 * q + 1] * 64 + m0 + r]);
    } else {
#pragma unroll
        for (int r = 0; r < RT; r++) {
            float b = bias_s[m0 + r];
            u64 bb = pack2(b, b);
#pragma unroll
            for (int q = 0; q < 4; q++) acc[r][q] = bb;
        }
    }
    float4 pf[LPT / 4];
#pragma unroll
    for (int f = 0; f < LPT / 4; f++)
        pf[f] = *reinterpret_cast<const float4*>(Wg + tid * LPT + 4 * f);
    stage_chunk<M>(Wbuf, pf, tid);
    __syncthreads();

    const uint32_t xb0 = sptr(Xs) + (uint32_t)p0 * 4u;
    const uint32_t wb0 = sptr(Wbuf) + (uint32_t)m0 * 4u;
#pragma unroll 1
    for (int c = 0; c < NC; c++) {
        if (c + 1 < NC) {
#pragma unroll
            for (int f = 0; f < LPT / 4; f++)
                pf[f] = *reinterpret_cast<const float4*>(Wg + (c + 1) * 16 * M + tid * LPT + 4 * f);
        }
        uint32_t wb = wb0 + (uint32_t)((c & 1) * 16 * M * 4);
        uint32_t xb = xb0 + (uint32_t)(c * 16 * PSTR * 4);
#pragma unroll
        for (int kk = 0; kk < 16; kk++) {
            u64 w[RT];
            if (RT == 4) {
                float4 wv; lds_f4(wv, wb + kk * M * 4);
                w[0] = pack2(wv.x, wv.x); w[1] = pack2(wv.y, wv.y);
                w[2] = pack2(wv.z, wv.z); w[3] = pack2(wv.w, wv.w);
            } else {
                float2 wv; lds_f2(wv, wb + kk * M * 4);
                w[0] = pack2(wv.x, wv.x); w[1] = pack2(wv.y, wv.y);
            }
            u64 x[4];
            lds_v2u64(x[0], x[1], xb + kk * PSTR * 4);
            lds_v2u64(x[2], x[3], xb + kk * PSTR * 4 + 16);
#pragma unroll
            for (int r = 0; r < RT; r++)
#pragma unroll
                for (int q = 0; q < 4; q++) ffma2(acc[r][q], w[r], x[q]);
        }
        if (c + 1 < NC) stage_chunk<M>(Wbuf + ((c + 1) & 1) * 16 * M, pf, tid);
        __syncthreads();
    }
#pragma unroll
    for (int r = 0; r < RT; r++) {
        float l0, h0, l1, h1, l2, h2, l3, h3;
        unpack2(l0, h0, acc[r][0]); unpack2(l1, h1, acc[r][1]);
        unpack2(l2, h2, acc[r][2]); unpack2(l3, h3, acc[r][3]);
        if (RELU) {
            l0 = fmaxf(l0, 0.f); h0 = fmaxf(h0, 0.f); l1 = fmaxf(l1, 0.f); h1 = fmaxf(h1, 0.f);
            l2 = fmaxf(l2, 0.f); h2 = fmaxf(h2, 0.f); l3 = fmaxf(l3, 0.f); h3 = fmaxf(h3, 0.f);
        }
        float4* yp = reinterpret_cast<float4*>(Ys + (m0 + r) * PSTR + p0);
        yp[0] = make_float4(l0, h0, l1, h1);
        yp[1] = make_float4(l2, h2, l3, h3);
    }
}

// smem layout (float offsets)
#define SA    0
#define SBUF  8704
#define SWB   17408
#define SB1   21504
#define SB2   21632
#define SBF   21760
#define SWSIG 21888
#define SWPTS 22016
#define SWC2  22112
#define SBC2  22304
#define SBSIG 22308
#define SPX   22312
#define SPY   22376
#define SPZ   22440
#define SVOX  22504
#define SRAY  22568
#define SCUR  22632
#define SMEM_MLP_BYTES ((SCUR + 4) * 4)

__global__ void __launch_bounds__(NTHR, 2)
mlp_kernel(const float* __restrict__ pts, const int* __restrict__ p2v,
           const float* __restrict__ vox_emb,
           const float* __restrict__ Wpts, const float* __restrict__ W1, const float* __restrict__ b1,
           const float* __restrict__ W2, const float* __restrict__ b2,
           const float* __restrict__ Wsig, const float* __restrict__ bsig,
           const float* __restrict__ Wfeat, const float* __restrict__ bfeat,
           const float* __restrict__ Wc1, const float* __restrict__ Wc2,
           const float* __restrict__ bc2) {
    extern __shared__ float sm[];
    float* A    = sm + SA;
    float* Bb   = sm + SBUF;
    float* Wbuf = sm + SWB;
    int* voxs   = (int*)(sm + SVOX);
    int* rays_s = (int*)(sm + SRAY);
    int* curp   = (int*)(sm + SCUR);
    const int tid = threadIdx.x;

    for (int i = tid; i < 128; i += NTHR) {
        sm[SB1 + i] = b1[i]; sm[SB2 + i] = b2[i];
        sm[SBF + i] = bfeat[i]; sm[SWSIG + i] = Wsig[i];
    }
    for (int i = tid; i < 96; i += NTHR)  sm[SWPTS + i] = Wpts[i];
    for (int i = tid; i < 192; i += NTHR) sm[SWC2 + i] = Wc2[i];
    if (tid < 3) sm[SBC2 + tid] = bc2[tid];
    if (tid == 0) sm[SBSIG] = bsig[0];
    __syncthreads();

    const int P = g_off[NRAYS];
    const int ntiles = (P + 63) >> 6;

    while (true) {
        if (tid == 0) *curp = atomicAdd(&g_tile_ctr, 1);
        __syncthreads();
        const int tile = *curp;
        if (tile >= ntiles) break;
        const int pbase = tile * 64;
        const int np = min(64, P - pbase);

        if (tid < 64) {
            if (tid < np) {
                int pid = pbase + tid;
                int ray = g_pray[pid];
                int base = ray * SMAX + (pid - g_off[ray]);
                voxs[tid]     = p2v[base];
                sm[SPX + tid] = pts[base * 3];
                sm[SPY + tid] = pts[base * 3 + 1];
                sm[SPZ + tid] = pts[base * 3 + 2];
                rays_s[tid]   = ray;
            } else {
                voxs[tid] = 0; rays_s[tid] = 0;
                sm[SPX + tid] = 0.f; sm[SPY + tid] = 0.f; sm[SPZ + tid] = 0.f;
            }
        }
        __syncthreads();

        {   // embed: A[k][p], k<32
            int kk = tid & 31, pg = tid >> 5;
            float wx = sm[SWPTS + kk], wy = sm[SWPTS + 32 + kk], wz = sm[SWPTS + 64 + kk];
#pragma unroll
            for (int q = 0; q < 8; q++) {
                int p = pg * 8 + q;
                A[kk * PSTR + p] = vox_emb[(size_t)voxs[p] * EMB + kk]
                                 + sm[SPX + p] * wx + sm[SPY + p] * wy + sm[SPZ + p] * wz;
            }
        }
        __syncthreads();

        gemm_layer<128, 32, true, false>(W1, A, Bb, sm + SB1, rays_s, Wbuf, tid);
        __syncthreads();
        gemm_layer<128, 128, true, false>(W2, Bb, A, sm + SB2, rays_s, Wbuf, tid);
        __syncthreads();

        if (tid < 64 && tid < np) {          // sigma from h2 (A)
            float a = sm[SBSIG];
#pragma unroll 16
            for (int k = 0; k < HID; k++) a += A[k * PSTR + tid] * sm[SWSIG + k];
            g_sig[pbase + tid] = a;
        }
        __syncthreads();

        gemm_layer<128, 128, false, false>(Wfeat, A, Bb, sm + SBF, rays_s, Wbuf, tid);
        __syncthreads();
        gemm_layer<64, 128, true, true>(Wc1, Bb, A, nullptr, rays_s, Wbuf, tid);
        __syncthreads();

        if (tid < 192) {                     // rgb = c1 @ Wc2 + bc2
            int p = tid & 63, ch = tid >> 6;
            if (p < np) {
                float a = sm[SBC2 + ch];
#pragma unroll 16
                for (int u = 0; u < 64; u++) a += A[u * PSTR + p] * sm[SWC2 + u * 3 + ch];
                g_rgbp[(size_t)(pbase + p) * 3 + ch] = a;
            }
        }
        __syncthreads();
    }
}

// ---------------- render: one warp per ray ----------------
__global__ void render_kernel(const float* __restrict__ t_vals, const float* __restrict__ dists,
                              float* __restrict__ out) {
    int gw = (blockIdx.x * blockDim.x + threadIdx.x) >> 5;
    int lane = threadIdx.x & 31;
    if (gw >= NRAYS) return;
    int off = g_off[gw], c = g_off[gw + 1] - off;

    float fe0 = 0.f, fe1 = 0.f, r0 = 0.f, g0 = 0.f, b0 = 0.f, r1 = 0.f, g1 = 0.f, b1v = 0.f;
    float t0 = 0.f, t1 = 0.f;
    if (lane < c) {
        fe0 = fmaxf(g_sig[off + lane], 0.f) * dists[gw * SMAX + lane];
        r0 = g_rgbp[(size_t)(off + lane) * 3];
        g0 = g_rgbp[(size_t)(off + lane) * 3 + 1];
        b0 = g_rgbp[(size_t)(off + lane) * 3 + 2];
        t0 = t_vals[gw * SMAX + lane];
    }
    int s1 = lane + 32;
    if (s1 < c) {
        fe1 = fmaxf(g_sig[off + s1], 0.f) * dists[gw * SMAX + s1];
        r1 = g_rgbp[(size_t)(off + s1) * 3];
        g1 = g_rgbp[(size_t)(off + s1) * 3 + 1];
        b1v = g_rgbp[(size_t)(off + s1) * 3 + 2];
        t1 = t_vals[gw * SMAX + s1];
    }
    float i0 = fe0;
#pragma unroll
    for (int d = 1; d < 32; d <<= 1) { float y = __shfl_up_sync(0xffffffffu, i0, d); if (lane >= d) i0 += y; }
    float tot0 = __shfl_sync(0xffffffffu, i0, 31);
    float i1 = fe1;
#pragma unroll
    for (int d = 1; d < 32; d <<= 1) { float y = __shfl_up_sync(0xffffffffu, i1, d); if (lane >= d) i1 += y; }
    float w0 = (1.f - expf(-fe0)) * expf(-(i0 - fe0));
    float w1 = (1.f - expf(-fe1)) * expf(-(tot0 + i1 - fe1));

    float cr = w0 * (r0 + 1.f) * 0.5f + w1 * (r1 + 1.f) * 0.5f;
    float cg = w0 * (g0 + 1.f) * 0.5f + w1 * (g1 + 1.f) * 0.5f;
    float cb = w0 * (b0 + 1.f) * 0.5f + w1 * (b1v + 1.f) * 0.5f;
    float ac = w0 + w1;
    float dp = w0 * t0 + w1 * t1;
#pragma unroll
    for (int d = 16; d; d >>= 1) {
        cr += __shfl_xor_sync(0xffffffffu, cr, d);
        cg += __shfl_xor_sync(0xffffffffu, cg, d);
        cb += __shfl_xor_sync(0xffffffffu, cb, d);
        ac += __shfl_xor_sync(0xffffffffu, ac, d);
        dp += __shfl_xor_sync(0xffffffffu, dp, d);
    }
    if (lane == 0) {
        if (c > 0) {
            float disp = 1.f / fmaxf(1e-10f, dp / fmaxf(ac, 1e-10f));
            out[gw * 3] = cr; out[gw * 3 + 1] = cg; out[gw * 3 + 2] = cb;
            out[3 * NRAYS + gw] = disp;
            out[4 * NRAYS + gw] = ac;
        } else {
            out[gw * 3] = 0.f; out[gw * 3 + 1] = 0.f; out[gw * 3 + 2] = 0.f;
            out[3 * NRAYS + gw] = 0.f;
            out[4 * NRAYS + gw] = 0.f;
        }
    }
}

extern "C" void kernel_launch(void* const* d_in, const int* in_sizes, int n_in,
                              void* d_out, int out_size) {
    const float *rays_d = 0, *pts = 0, *t_vals = 0, *dists = 0, *vox = 0, *Wpts = 0;
    const float *W1 = 0, *b1 = 0, *W2 = 0, *b2 = 0, *Wsig = 0, *bsig = 0;
    const float *Wfeat = 0, *bfeat = 0, *Wc1 = 0, *bc1 = 0, *Wc2 = 0, *bc2 = 0;
    const int* p2v = 0;
    int n524 = 0, n16384 = 0, n128 = 0;
    for (int i = 0; i < n_in; i++) {
        const void* p = d_in[i];
        switch (in_sizes[i]) {
            case 24576:   rays_d = (const float*)p; break;
            case 1572864: pts    = (const float*)p; break;
            case 524288:
                if (n524 == 0) t_vals = (const float*)p;
                else if (n524 == 1) dists = (const float*)p;
                else p2v = (const int*)p;
                n524++; break;
            case 3200000: vox = (const float*)p; break;
            case 96:    Wpts = (const float*)p; break;
            case 4096:  W1 = (const float*)p; break;
            case 128:
                if (n128 == 0) b1 = (const float*)p;
                else if (n128 == 1) b2 = (const float*)p;
                else if (n128 == 2) Wsig = (const float*)p;
                else bfeat = (const float*)p;
                n128++; break;
            case 16384:
                if (n16384 == 0) W2 = (const float*)p; else Wfeat = (const float*)p;
                n16384++; break;
            case 1:    bsig = (const float*)p; break;
            case 9920: Wc1 = (const float*)p; break;
            case 64:   bc1 = (const float*)p; break;
            case 192:  Wc2 = (const float*)p; break;
            case 3:    bc2 = (const float*)p; break;
            default: break; // 8192 = ray_hits, derived from p2v
        }
    }
    static int smem_set = 0;
    if (!smem_set) {
        cudaFuncSetAttribute(mlp_kernel, cudaFuncAttributeMaxDynamicSharedMemorySize, SMEM_MLP_BYTES);
        smem_set = 1;
    }
    prep_ray_kernel<<<NRAYS / 256, 256>>>(p2v, rays_d);
    scan_kernel<<<1, 1024>>>();
    vb_kernel<<<(NRAYS * 64) / 256, 256>>>(Wc1, bc1);
    pray_kernel<<<NRAYS / 4, 256>>>();
    mlp_kernel<<<296, NTHR, SMEM_MLP_BYTES>>>(pts, p2v, vox, Wpts, W1, b1, W2, b2,
                                              Wsig, bsig, Wfeat, bfeat, Wc1, Wc2, bc2);
    render_kernel<<<NRAYS / 8, 256>>>(t_vals, dists, (float*)d_out);
}

// round 10
// speedup vs baseline: 5.1056x; 2.8532x over previous
#include <cuda_runtime.h>
#include <cuda_bf16.h>
#include <math.h>
#include <stdint.h>

#define NRAYS 8192
#define SMAX  64

// ---------------- global scratch ----------------
__device__ int      g_cnt[NRAYS];
__device__ int      g_off[NRAYS + 1];
__device__ int      g_pray[NRAYS * SMAX];
__device__ float    g_vemb[NRAYS * 27];
__device__ float    g_sig[NRAYS * SMAX];
__device__ float    g_rgbp[NRAYS * SMAX * 3];
__device__ uint32_t g_wimgu[47104];   // packed bf16 hi/lo weight image, fragment-linear
__device__ int      g_tile_ctr;

// image layout (u32 words): per (kstep s, Mtile mt): 256 words =
// [hi: lane*4+reg (128)][lo: 128 + lane*4+reg]; blocks ordered blk = s*MT + mt.
// L1 @0 (MT8,S2)=4096 | L2 @4096 (MT8,S8)=16384 | L3 @20480 (MT8,S8)=16384 | L4 @36864 (MT4,S10)=10240

__device__ __forceinline__ uint32_t packsplit(float y) {
    unsigned short h = __bfloat16_as_ushort(__float2bfloat16(y));
    float hf = __uint_as_float((uint32_t)h << 16);
    unsigned short l = __bfloat16_as_ushort(__float2bfloat16(y - hf));
    return ((uint32_t)h << 16) | l;
}
__device__ __forceinline__ void mma_bf16(float (&c)[4], const uint32_t (&a)[4],
                                         uint32_t b0, uint32_t b1) {
    asm volatile("mma.sync.aligned.m16n8k16.row.col.f32.bf16.bf16.f32 "
        "{%0,%1,%2,%3}, {%4,%5,%6,%7}, {%8,%9}, {%0,%1,%2,%3};"
        : "+f"(c[0]), "+f"(c[1]), "+f"(c[2]), "+f"(c[3])
        : "r"(a[0]), "r"(a[1]), "r"(a[2]), "r"(a[3]), "r"(b0), "r"(b1));
}

// ---------------- setup kernels ----------------
__global__ void prep_ray_kernel(const int* __restrict__ p2v, const float* __restrict__ rays_d) {
    int r = blockIdx.x * blockDim.x + threadIdx.x;
    if (r >= NRAYS) return;
    int lo = 0, hi = SMAX;
    while (lo < hi) {                       // valid samples form a prefix
        int mid = (lo + hi) >> 1;
        if (p2v[r * SMAX + mid] >= 0) lo = mid + 1; else hi = mid;
    }
    g_cnt[r] = lo;
    float dv[3] = {rays_d[r * 3], rays_d[r * 3 + 1], rays_d[r * 3 + 2]};
    g_vemb[r * 27 + 0] = dv[0]; g_vemb[r * 27 + 1] = dv[1]; g_vemb[r * 27 + 2] = dv[2];
#pragma unroll
    for (int i = 0; i < 3; i++)
#pragma unroll
        for (int l = 0; l < 4; l++) {
            float ang = dv[i] * (float)(1 << l);
            g_vemb[r * 27 + 3 + i * 4 + l]  = sinf(ang);
            g_vemb[r * 27 + 15 + i * 4 + l] = cosf(ang);
        }
}

__global__ void scan_kernel() {
    __shared__ int wsum[32];
    int t = threadIdx.x;
    int v[8]; int s = 0;
#pragma unroll
    for (int i = 0; i < 8; i++) { v[i] = g_cnt[t * 8 + i]; s += v[i]; }
    int lane = t & 31, wid = t >> 5;
    int x = s;
#pragma unroll
    for (int d = 1; d < 32; d <<= 1) { int y = __shfl_up_sync(0xffffffffu, x, d); if (lane >= d) x += y; }
    if (lane == 31) wsum[wid] = x;
    __syncthreads();
    if (wid == 0) {
        int y = wsum[lane];
#pragma unroll
        for (int d = 1; d < 32; d <<= 1) { int z = __shfl_up_sync(0xffffffffu, y, d); if (lane >= d) y += z; }
        wsum[lane] = y;
    }
    __syncthreads();
    int run = (wid > 0 ? wsum[wid - 1] : 0) + x - s;
#pragma unroll
    for (int i = 0; i < 8; i++) { g_off[t * 8 + i] = run; run += v[i]; }
    if (t == 1023) { g_off[NRAYS] = run; g_tile_ctr = 0; }
}

__global__ void pray_kernel() {
    int r = blockIdx.x * 4 + (threadIdx.x >> 6);
    int t = threadIdx.x & 63;
    int o = g_off[r], c = g_off[r + 1] - o;
    if (t < c) g_pray[o + t] = r;
}

// weights (k-major [K][units]) -> packed bf16 hi/lo fragment image
__global__ void wimg_kernel(const float* __restrict__ W1, const float* __restrict__ W2,
                            const float* __restrict__ Wf, const float* __restrict__ Wc1) {
    int idx = blockIdx.x * 256 + threadIdx.x;
    if (idx >= 47104) return;
    int layer, rel, MT;
    if (idx < 4096)       { layer = 0; rel = idx;         MT = 8; }
    else if (idx < 20480) { layer = 1; rel = idx - 4096;  MT = 8; }
    else if (idx < 36864) { layer = 2; rel = idx - 20480; MT = 8; }
    else                  { layer = 3; rel = idx - 36864; MT = 4; }
    int blk = rel >> 8, within = rel & 255;
    int half = within >> 7, lr = within & 127;
    int lane = lr >> 2, r = lr & 3;
    int s = blk / MT, mt = blk % MT;
    int g = lane >> 2, tg = lane & 3;
    int row = g + (r & 1) * 8;
    int kk = 2 * tg + (r >> 1) * 8;
    int u = mt * 16 + row;
    int k = s * 16 + kk;
    float x0, x1;
    if (layer == 0)      { x0 = W1[k * 128 + u]; x1 = W1[(k + 1) * 128 + u]; }
    else if (layer == 1) { x0 = W2[k * 128 + u]; x1 = W2[(k + 1) * 128 + u]; }
    else if (layer == 2) { x0 = Wf[k * 128 + u]; x1 = Wf[(k + 1) * 128 + u]; }
    else { x0 = (k < 155) ? Wc1[k * 64 + u] : 0.f; x1 = (k + 1 < 155) ? Wc1[(k + 1) * 64 + u] : 0.f; }
    unsigned short h0 = __bfloat16_as_ushort(__float2bfloat16(x0));
    unsigned short h1 = __bfloat16_as_ushort(__float2bfloat16(x1));
    uint32_t w;
    if (half == 0) {
        w = ((uint32_t)h1 << 16) | h0;
    } else {
        float r0 = x0 - __uint_as_float((uint32_t)h0 << 16);
        float r1 = x1 - __uint_as_float((uint32_t)h1 << 16);
        unsigned short l0 = __bfloat16_as_ushort(__float2bfloat16(r0));
        unsigned short l1 = __bfloat16_as_ushort(__float2bfloat16(r1));
        w = ((uint32_t)l1 << 16) | l0;
    }
    g_wimgu[idx] = w;
}

// ---------------- MLP kernel ----------------
// smem word offsets
#define BUFA_W  0        // [64 pts][136] packed hi/lo words (X0:K32, h2:K128) / c1 fp32 [64][68]
#define BUFB_W  8704     // [64 pts][168] packed (h1:K128, feat+vemb:K160)
#define WBUF_W  19456    // 2 x 2048 word chunk DB
#define SB1_W   23552
#define SB2_W   23680
#define SBF_W   23808
#define SBC1_W  23936
#define SWSIG_W 24000
#define SWC2_W  24128
#define SWPTS_W 24320
#define SBC2_W  24416
#define SBSIG_W 24419
#define SPX_W   24420
#define SPY_W   24484
#define SPZ_W   24548
#define SVOX_W  24612
#define SRAY_W  24676
#define SCUR_W  24740
#define SMEM_WORDS 24744
#define SMEM_MLP_BYTES (SMEM_WORDS * 4)

#define KPA 136   // 136 % 32 == 8 -> conflict-free B-frag LDS.64
#define KPB 168   // 168 % 32 == 8

template <int MT, int NSTEPS, int KPIN>
__device__ __forceinline__ void layer_mma(const uint32_t* __restrict__ gimg,
                                          uint32_t* __restrict__ wbuf,
                                          const uint32_t* __restrict__ xin,
                                          float (&C)[2][8][4],
                                          int tid, int wid, int lane) {
    constexpr int CH  = MT * 256;          // words per kstep
    constexpr int LPT = CH / 512;          // float4 per thread per stage (4 or 2)
    const int g = lane >> 2, tg = lane & 3;
#pragma unroll
    for (int a = 0; a < 2; a++)
#pragma unroll
        for (int b = 0; b < 8; b++)
#pragma unroll
            for (int c = 0; c < 4; c++) C[a][b][c] = 0.f;
    {
        const float4* src = (const float4*)gimg;
        float4* dst = (float4*)wbuf;
#pragma unroll
        for (int i = 0; i < LPT; i++) dst[tid + i * 128] = src[tid + i * 128];
    }
    __syncthreads();
#pragma unroll 1
    for (int s = 0; s < NSTEPS; s++) {
        float4 pf[LPT];
        if (s + 1 < NSTEPS) {
            const float4* src = (const float4*)(gimg + (s + 1) * CH);
#pragma unroll
            for (int i = 0; i < LPT; i++) pf[i] = src[tid + i * 128];
        }
        const uint32_t* wb = wbuf + (s & 1) * CH;
        uint32_t Ahi[2][4], Alo[2][4];
        const int NMI = (MT == 8) ? 2 : 1;
#pragma unroll
        for (int mi = 0; mi < NMI; mi++) {
            int mt = (MT == 8) ? (wid + mi * 4) : wid;
            const uint32_t* fb = wb + mt * 256;
            *(uint4*)Ahi[mi] = *(const uint4*)(fb + lane * 4);
            *(uint4*)Alo[mi] = *(const uint4*)(fb + 128 + lane * 4);
        }
        const uint32_t* xk = xin + s * 16 + 2 * tg;
#pragma unroll
        for (int nt = 0; nt < 8; nt++) {
            int pt = nt * 8 + g;
            const uint32_t* xr = xk + pt * KPIN;
            uint2 d0 = *(const uint2*)xr;
            uint2 d1 = *(const uint2*)(xr + 8);
            uint32_t bh0 = __byte_perm(d0.x, d0.y, 0x7632);
            uint32_t bl0 = __byte_perm(d0.x, d0.y, 0x5410);
            uint32_t bh1 = __byte_perm(d1.x, d1.y, 0x7632);
            uint32_t bl1 = __byte_perm(d1.x, d1.y, 0x5410);
#pragma unroll
            for (int mi = 0; mi < NMI; mi++) {
                mma_bf16(C[mi][nt], Ahi[mi], bh0, bh1);
                mma_bf16(C[mi][nt], Ahi[mi], bl0, bl1);
                mma_bf16(C[mi][nt], Alo[mi], bh0, bh1);
            }
        }
        if (s + 1 < NSTEPS) {
            float4* dst = (float4*)(wbuf + ((s + 1) & 1) * CH);
#pragma unroll
            for (int i = 0; i < LPT; i++) dst[tid + i * 128] = pf[i];
        }
        __syncthreads();
    }
}

template <int MTILES, bool RELU>
__device__ __forceinline__ void epi_pack(float (&C)[2][8][4], const float* __restrict__ bias,
                                         uint32_t* __restrict__ xout, int KPOUT,
                                         int wid, int lane) {
    int g = lane >> 2, tg = lane & 3;
#pragma unroll
    for (int mi = 0; mi < MTILES; mi++) {
        int mt = (MTILES == 2) ? (wid + mi * 4) : wid;
        int r0 = mt * 16 + g, r1 = r0 + 8;
        float b0 = bias[r0], b1 = bias[r1];
#pragma unroll
        for (int nt = 0; nt < 8; nt++) {
            int p0 = nt * 8 + 2 * tg;
            float y00 = C[mi][nt][0] + b0, y01 = C[mi][nt][1] + b0;
            float y10 = C[mi][nt][2] + b1, y11 = C[mi][nt][3] + b1;
            if (RELU) {
                y00 = fmaxf(y00, 0.f); y01 = fmaxf(y01, 0.f);
                y10 = fmaxf(y10, 0.f); y11 = fmaxf(y11, 0.f);
            }
            xout[p0 * KPOUT + r0]       = packsplit(y00);
            xout[(p0 + 1) * KPOUT + r0] = packsplit(y01);
            xout[p0 * KPOUT + r1]       = packsplit(y10);
            xout[(p0 + 1) * KPOUT + r1] = packsplit(y11);
        }
    }
}

__global__ void __launch_bounds__(128, 2)
mlp_kernel(const float* __restrict__ pts, const int* __restrict__ p2v,
           const float* __restrict__ vox_emb, const float* __restrict__ Wpts,
           const float* __restrict__ b1, const float* __restrict__ b2,
           const float* __restrict__ Wsig, const float* __restrict__ bsig,
           const float* __restrict__ bfeat, const float* __restrict__ bc1,
           const float* __restrict__ Wc2, const float* __restrict__ bc2) {
    extern __shared__ uint32_t smu[];
    float* smf = (float*)smu;
    uint32_t* bufA = smu + BUFA_W;
    uint32_t* bufB = smu + BUFB_W;
    uint32_t* wbuf = smu + WBUF_W;
    float* c1f = (float*)(smu + BUFA_W);
    int* voxs   = (int*)(smu + SVOX_W);
    int* rays_s = (int*)(smu + SRAY_W);
    int* curp   = (int*)(smu + SCUR_W);
    const int tid = threadIdx.x;
    const int wid = tid >> 5, lane = tid & 31;

    for (int i = tid; i < 128; i += 128) {
        smf[SB1_W + i] = b1[i]; smf[SB2_W + i] = b2[i];
        smf[SBF_W + i] = bfeat[i]; smf[SWSIG_W + i] = Wsig[i];
    }
    if (tid < 64) smf[SBC1_W + tid] = bc1[tid];
    if (tid < 96) smf[SWPTS_W + tid] = Wpts[tid];
    for (int i = tid; i < 192; i += 128) smf[SWC2_W + i] = Wc2[i];
    if (tid < 3)  smf[SBC2_W + tid] = bc2[tid];
    if (tid == 0) smf[SBSIG_W] = bsig[0];

    const int P = g_off[NRAYS];
    const int ntiles = (P + 63) >> 6;
    float C[2][8][4];

    while (true) {
        __syncthreads();
        if (tid == 0) *curp = atomicAdd(&g_tile_ctr, 1);
        __syncthreads();
        const int tile = *curp;
        if (tile >= ntiles) break;
        const int pbase = tile * 64;
        const int np = min(64, P - pbase);

        // ---- tile meta ----
        if (tid < 64) {
            if (tid < np) {
                int pid = pbase + tid;
                int ray = g_pray[pid];
                int base = ray * SMAX + (pid - g_off[ray]);
                voxs[tid] = p2v[base];
                smf[SPX_W + tid] = pts[base * 3];
                smf[SPY_W + tid] = pts[base * 3 + 1];
                smf[SPZ_W + tid] = pts[base * 3 + 2];
                rays_s[tid] = ray;
            } else {
                voxs[tid] = 0; rays_s[tid] = 0;
                smf[SPX_W + tid] = 0.f; smf[SPY_W + tid] = 0.f; smf[SPZ_W + tid] = 0.f;
            }
        }
        __syncthreads();

        // ---- embed -> bufA [pt][k<32]; vemb -> bufB [pt][128+j] ----
        {
            int pt = tid >> 1, kh = (tid & 1) * 16;
            int v = voxs[pt];
            float px = smf[SPX_W + pt], py = smf[SPY_W + pt], pz = smf[SPZ_W + pt];
            const float* vrow = vox_emb + (size_t)v * 32;
#pragma unroll
            for (int q = 0; q < 16; q++) {
                int k = kh + q;
                float val = vrow[k] + px * smf[SWPTS_W + k]
                          + py * smf[SWPTS_W + 32 + k] + pz * smf[SWPTS_W + 64 + k];
                bufA[pt * KPA + k] = packsplit(val);
            }
            int ray = rays_s[pt];
#pragma unroll
            for (int q = 0; q < 16; q++) {
                int j = kh + q;
                float val = (j < 27) ? g_vemb[ray * 27 + j] : 0.f;
                bufB[pt * KPB + 128 + j] = packsplit(val);
            }
        }
        // (layer_mma's internal first sync orders these writes before mma reads)

        layer_mma<8, 2, KPA>(g_wimgu,         wbuf, bufA, C, tid, wid, lane);   // h1
        epi_pack<2, true>(C, smf + SB1_W, bufB, KPB, wid, lane);
        layer_mma<8, 8, KPB>(g_wimgu + 4096,  wbuf, bufB, C, tid, wid, lane);   // h2
        epi_pack<2, true>(C, smf + SB2_W, bufA, KPA, wid, lane);
        __syncthreads();

        // ---- sigma from h2 (bufA packed) ----
        if (tid < np) {
            float a = smf[SBSIG_W];
#pragma unroll 8
            for (int k = 0; k < 128; k++) {
                uint32_t w = bufA[tid * KPA + k];
                float val = __uint_as_float(w & 0xffff0000u) + __uint_as_float(w << 16);
                a += val * smf[SWSIG_W + k];
            }
            g_sig[pbase + tid] = a;
        }

        layer_mma<8, 8, KPA>(g_wimgu + 20480, wbuf, bufA, C, tid, wid, lane);   // feat
        epi_pack<2, false>(C, smf + SBF_W, bufB, KPB, wid, lane);
        layer_mma<4, 10, KPB>(g_wimgu + 36864, wbuf, bufB, C, tid, wid, lane);  // c1
        // L4 epilogue: fp32 c1 -> bufA as float [pt][68]
        {
            int g = lane >> 2, tg = lane & 3;
            int r0 = wid * 16 + g, r1 = r0 + 8;
            float bb0 = smf[SBC1_W + r0], bb1 = smf[SBC1_W + r1];
#pragma unroll
            for (int nt = 0; nt < 8; nt++) {
                int p0 = nt * 8 + 2 * tg;
                c1f[p0 * 68 + r0]       = fmaxf(C[0][nt][0] + bb0, 0.f);
                c1f[(p0 + 1) * 68 + r0] = fmaxf(C[0][nt][1] + bb0, 0.f);
                c1f[p0 * 68 + r1]       = fmaxf(C[0][nt][2] + bb1, 0.f);
                c1f[(p0 + 1) * 68 + r1] = fmaxf(C[0][nt][3] + bb1, 0.f);
            }
        }
        __syncthreads();

        // ---- rgb = c1 @ Wc2 + bc2 ----
        if (tid < np) {
            float a0 = smf[SBC2_W], a1 = smf[SBC2_W + 1], a2 = smf[SBC2_W + 2];
#pragma unroll 8
            for (int u = 0; u < 64; u++) {
                float cv = c1f[tid * 68 + u];
                a0 += cv * smf[SWC2_W + u * 3];
                a1 += cv * smf[SWC2_W + u * 3 + 1];
                a2 += cv * smf[SWC2_W + u * 3 + 2];
            }
            size_t o3 = (size_t)(pbase + tid) * 3;
            g_rgbp[o3] = a0; g_rgbp[o3 + 1] = a1; g_rgbp[o3 + 2] = a2;
        }
    }
}

// ---------------- render: one warp per ray ----------------
__global__ void render_kernel(const float* __restrict__ t_vals, const float* __restrict__ dists,
                              float* __restrict__ out) {
    int gw = (blockIdx.x * blockDim.x + threadIdx.x) >> 5;
    int lane = threadIdx.x & 31;
    if (gw >= NRAYS) return;
    int off = g_off[gw], c = g_off[gw + 1] - off;

    float fe0 = 0.f, fe1 = 0.f, r0 = 0.f, g0 = 0.f, b0 = 0.f, r1 = 0.f, g1 = 0.f, b1v = 0.f;
    float t0 = 0.f, t1 = 0.f;
    if (lane < c) {
        fe0 = fmaxf(g_sig[off + lane], 0.f) * dists[gw * SMAX + lane];
        r0 = g_rgbp[(size_t)(off + lane) * 3];
        g0 = g_rgbp[(size_t)(off + lane) * 3 + 1];
        b0 = g_rgbp[(size_t)(off + lane) * 3 + 2];
        t0 = t_vals[gw * SMAX + lane];
    }
    int s1 = lane + 32;
    if (s1 < c) {
        fe1 = fmaxf(g_sig[off + s1], 0.f) * dists[gw * SMAX + s1];
        r1 = g_rgbp[(size_t)(off + s1) * 3];
        g1 = g_rgbp[(size_t)(off + s1) * 3 + 1];
        b1v = g_rgbp[(size_t)(off + s1) * 3 + 2];
        t1 = t_vals[gw * SMAX + s1];
    }
    float i0 = fe0;
#pragma unroll
    for (int d = 1; d < 32; d <<= 1) { float y = __shfl_up_sync(0xffffffffu, i0, d); if (lane >= d) i0 += y; }
    float tot0 = __shfl_sync(0xffffffffu, i0, 31);
    float i1 = fe1;
#pragma unroll
    for (int d = 1; d < 32; d <<= 1) { float y = __shfl_up_sync(0xffffffffu, i1, d); if (lane >= d) i1 += y; }
    float w0 = (1.f - expf(-fe0)) * expf(-(i0 - fe0));
    float w1 = (1.f - expf(-fe1)) * expf(-(tot0 + i1 - fe1));

    float cr = w0 * (r0 + 1.f) * 0.5f + w1 * (r1 + 1.f) * 0.5f;
    float cg = w0 * (g0 + 1.f) * 0.5f + w1 * (g1 + 1.f) * 0.5f;
    float cb = w0 * (b0 + 1.f) * 0.5f + w1 * (b1v + 1.f) * 0.5f;
    float ac = w0 + w1;
    float dp = w0 * t0 + w1 * t1;
#pragma unroll
    for (int d = 16; d; d >>= 1) {
        cr += __shfl_xor_sync(0xffffffffu, cr, d);
        cg += __shfl_xor_sync(0xffffffffu, cg, d);
        cb += __shfl_xor_sync(0xffffffffu, cb, d);
        ac += __shfl_xor_sync(0xffffffffu, ac, d);
        dp += __shfl_xor_sync(0xffffffffu, dp, d);
    }
    if (lane == 0) {
        if (c > 0) {
            float disp = 1.f / fmaxf(1e-10f, dp / fmaxf(ac, 1e-10f));
            out[gw * 3] = cr; out[gw * 3 + 1] = cg; out[gw * 3 + 2] = cb;
            out[3 * NRAYS + gw] = disp;
            out[4 * NRAYS + gw] = ac;
        } else {
            out[gw * 3] = 0.f; out[gw * 3 + 1] = 0.f; out[gw * 3 + 2] = 0.f;
            out[3 * NRAYS + gw] = 0.f;
            out[4 * NRAYS + gw] = 0.f;
        }
    }
}

extern "C" void kernel_launch(void* const* d_in, const int* in_sizes, int n_in,
                              void* d_out, int out_size) {
    const float *rays_d = 0, *pts = 0, *t_vals = 0, *dists = 0, *vox = 0, *Wpts = 0;
    const float *W1 = 0, *b1 = 0, *W2 = 0, *b2 = 0, *Wsig = 0, *bsig = 0;
    const float *Wfeat = 0, *bfeat = 0, *Wc1 = 0, *bc1 = 0, *Wc2 = 0, *bc2 = 0;
    const int* p2v = 0;
    int n524 = 0, n16384 = 0, n128 = 0;
    for (int i = 0; i < n_in; i++) {
        const void* p = d_in[i];
        switch (in_sizes[i]) {
            case 24576:   rays_d = (const float*)p; break;
            case 1572864: pts    = (const float*)p; break;
            case 524288:
                if (n524 == 0) t_vals = (const float*)p;
                else if (n524 == 1) dists = (const float*)p;
                else p2v = (const int*)p;
                n524++; break;
            case 3200000: vox = (const float*)p; break;
            case 96:    Wpts = (const float*)p; break;
            case 4096:  W1 = (const float*)p; break;
            case 128:
                if (n128 == 0) b1 = (const float*)p;
                else if (n128 == 1) b2 = (const float*)p;
                else if (n128 == 2) Wsig = (const float*)p;
                else bfeat = (const float*)p;
                n128++; break;
            case 16384:
                if (n16384 == 0) W2 = (const float*)p; else Wfeat = (const float*)p;
                n16384++; break;
            case 1:    bsig = (const float*)p; break;
            case 9920: Wc1 = (const float*)p; break;
            case 64:   bc1 = (const float*)p; break;
            case 192:  Wc2 = (const float*)p; break;
            case 3:    bc2 = (const float*)p; break;
            default: break; // 8192 = ray_hits, derived from p2v
        }
    }
    static int smem_set = 0;
    if (!smem_set) {
        cudaFuncSetAttribute(mlp_kernel, cudaFuncAttributeMaxDynamicSharedMemorySize, SMEM_MLP_BYTES);
        smem_set = 1;
    }
    prep_ray_kernel<<<NRAYS / 256, 256>>>(p2v, rays_d);
    scan_kernel<<<1, 1024>>>();
    wimg_kernel<<<184, 256>>>(W1, W2, Wfeat, Wc1);
    pray_kernel<<<NRAYS / 4, 256>>>();
    mlp_kernel<<<296, 128, SMEM_MLP_BYTES>>>(pts, p2v, vox, Wpts, b1, b2, Wsig, bsig,
                                             bfeat, bc1, Wc2, bc2);
    render_kernel<<<NRAYS / 8, 256>>>(t_vals, dists, (float*)d_out);
}